// round 3
// baseline (speedup 1.0000x reference)
#include <cuda_runtime.h>

// Problem constants
#define NN   4
#define CC   256
#define HS   64
#define WS   64
#define PIX  4096
#define COMPC 64
#define MC   100      // K*K*R*R
#define KK2  25
#define HO   128
#define WO   128
#define OPIX 16384
#define BN_EPS 1e-5f

// ---------------- device scratch (no allocation allowed) ----------------
__device__ float g_comp[NN * COMPC * PIX];         // compressed features
__device__ float g_mlog[NN * MC * PIX];            // encoder logits
__device__ float g_mask[NN * HO * WO * KK2];       // softmaxed masks, [n][i][j][k]
__device__ float g_y   [NN * CC * PIX];            // W_eff @ high
__device__ float g_weff[CC * CC];
__device__ float g_beff[CC];
__device__ float g_sum [CC];
__device__ float g_sumsq[CC];
__device__ float g_scale[CC];
__device__ float g_shift[CC];

// ---------------- K0: fold weights + zero BN accumulators ----------------
// W_eff[o][c] = sum_m w_bott[o][m] * w_conv2[m][c] + w_bott[o][256+c]
// b_eff[o]    = sum_m w_bott[o][m] * b_conv2[m]
__global__ void k_fold(const float* __restrict__ wb,
                       const float* __restrict__ wc2,
                       const float* __restrict__ bc2) {
    int o = blockIdx.x;
    int c = threadIdx.x;
    const float* wbo = wb + o * 512;
    float acc = wbo[256 + c];
    for (int m = 0; m < 256; m++)
        acc += wbo[m] * wc2[m * 256 + c];
    g_weff[o * 256 + c] = acc;

    __shared__ float red[256];
    red[c] = wbo[c] * bc2[c];
    __syncthreads();
    for (int s = 128; s > 0; s >>= 1) {
        if (c < s) red[c] += red[c + s];
        __syncthreads();
    }
    if (c == 0) g_beff[o] = red[0];
    if (o == 0) { g_sum[c] = 0.f; g_sumsq[c] = 0.f; }
}

// ---------------- K1: merged compress(64) + ymix(256) GEMM, M=320 K=256 ----------------
// grid 320 = mt(5 of 64 rows) x pt(16 px tiles of 256) x n(4); 256 threads
// thread: 8 oc x 8 px register tile; float4 LDS for both operands
__global__ __launch_bounds__(256) void k_gemm(const float* __restrict__ hi,
                                              const float* __restrict__ wcc,
                                              const float* __restrict__ bcc) {
    int b  = blockIdx.x;
    int mt = b % 5;
    int pt = (b / 5) & 15;
    int n  = b / 80;
    int px0 = pt * 256;
    int tid = threadIdx.x;
    int tx = tid & 31, og = tid >> 5;
    int pxl = tx * 8, ocl = og * 8;

    __shared__ __align__(16) float ws[16][64];
    __shared__ __align__(16) float xs[16][256];

    float acc[8][8];
    #pragma unroll
    for (int o = 0; o < 8; o++)
        #pragma unroll
        for (int p = 0; p < 8; p++) acc[o][p] = 0.f;

    int m_l = tid >> 2, kq = tid & 3;
    int m_g = mt * 64 + m_l;
    const float* wsrc = (m_g < 64) ? (wcc + m_g * 256) : (g_weff + (m_g - 64) * 256);
    const float* xsrc = hi + n * 256 * PIX + px0;

    for (int k0 = 0; k0 < 256; k0 += 16) {
        float4 wv = *(const float4*)(wsrc + k0 + kq * 4);
        float4 xv[4];
        #pragma unroll
        for (int l = 0; l < 4; l++) {
            int fi = tid + l * 256;
            int kr = fi >> 6, pq = fi & 63;
            xv[l] = *(const float4*)(xsrc + (k0 + kr) * PIX + pq * 4);
        }
        __syncthreads();
        ws[kq * 4 + 0][m_l] = wv.x;
        ws[kq * 4 + 1][m_l] = wv.y;
        ws[kq * 4 + 2][m_l] = wv.z;
        ws[kq * 4 + 3][m_l] = wv.w;
        #pragma unroll
        for (int l = 0; l < 4; l++) {
            int fi = tid + l * 256;
            int kr = fi >> 6, pq = fi & 63;
            *(float4*)&xs[kr][pq * 4] = xv[l];
        }
        __syncthreads();

        #pragma unroll
        for (int kr = 0; kr < 16; kr++) {
            float4 xa = *(const float4*)&xs[kr][pxl];
            float4 xb = *(const float4*)&xs[kr][pxl + 4];
            float4 wa = *(const float4*)&ws[kr][ocl];
            float4 wb2 = *(const float4*)&ws[kr][ocl + 4];
            float wv_[8] = { wa.x, wa.y, wa.z, wa.w, wb2.x, wb2.y, wb2.z, wb2.w };
            float xv_[8] = { xa.x, xa.y, xa.z, xa.w, xb.x, xb.y, xb.z, xb.w };
            #pragma unroll
            for (int o = 0; o < 8; o++)
                #pragma unroll
                for (int p = 0; p < 8; p++)
                    acc[o][p] += wv_[o] * xv_[p];
        }
    }

    #pragma unroll
    for (int o = 0; o < 8; o++) {
        int m = mt * 64 + ocl + o;
        float bias = (m < 64) ? bcc[m] : 0.f;
        float4 v0 = make_float4(acc[o][0] + bias, acc[o][1] + bias,
                                acc[o][2] + bias, acc[o][3] + bias);
        float4 v1 = make_float4(acc[o][4] + bias, acc[o][5] + bias,
                                acc[o][6] + bias, acc[o][7] + bias);
        float* dst = (m < 64) ? (g_comp + (n * 64 + m) * PIX + px0 + pxl)
                              : (g_y + (n * 256 + (m - 64)) * PIX + px0 + pxl);
        *(float4*)(dst)     = v0;
        *(float4*)(dst + 4) = v1;
    }
}

// ---------------- K2: content encoder 3x3 (64 -> 100) [R1 version] ----------------
// grid 256 = (n,h); 128 threads: w-pair x 25 oc group (tid>>5)
__global__ __launch_bounds__(128) void k_encode(const float* __restrict__ wce,
                                                const float* __restrict__ bce) {
    int b = blockIdx.x; int n = b >> 6; int h = b & 63;
    int tid = threadIdx.x;
    int w2 = tid & 31; int og = tid >> 5;
    __shared__ float xs[8][3][66];
    __shared__ float ws[100 * 72];
    float acc0[25], acc1[25];
    #pragma unroll
    for (int o = 0; o < 25; o++) { acc0[o] = 0.f; acc1[o] = 0.f; }

    for (int cc0 = 0; cc0 < 64; cc0 += 8) {
        for (int idx = tid; idx < 8 * 3 * 66; idx += 128) {
            int cl = idx / 198; int rem = idx % 198; int r = rem / 66; int x = rem % 66;
            int gh = h - 1 + r, gw = x - 1;
            float v = 0.f;
            if (gh >= 0 && gh < 64 && gw >= 0 && gw < 64)
                v = g_comp[((n * COMPC + cc0 + cl) * HS + gh) * WS + gw];
            xs[cl][r][x] = v;
        }
        for (int idx = tid; idx < 7200; idx += 128) {
            int oc = idx / 72; int r = idx % 72;
            ws[idx] = wce[oc * 576 + cc0 * 9 + r];
        }
        __syncthreads();
        for (int cl = 0; cl < 8; cl++) {
            #pragma unroll
            for (int ky = 0; ky < 3; ky++) {
                #pragma unroll
                for (int kx = 0; kx < 3; kx++) {
                    float x0 = xs[cl][ky][w2 + kx];
                    float x1 = xs[cl][ky][w2 + 32 + kx];
                    int wbase = og * 25 * 72 + cl * 9 + ky * 3 + kx;
                    #pragma unroll
                    for (int o = 0; o < 25; o++) {
                        float wv = ws[wbase + o * 72];
                        acc0[o] += wv * x0;
                        acc1[o] += wv * x1;
                    }
                }
            }
        }
        __syncthreads();
    }
    #pragma unroll
    for (int o = 0; o < 25; o++) {
        int oc = og * 25 + o;
        float bv = bce[oc];
        g_mlog[((n * MC + oc) * HS + h) * WS + w2]      = acc0[o] + bv;
        g_mlog[((n * MC + oc) * HS + h) * WS + w2 + 32] = acc1[o] + bv;
    }
}

// ---------------- K3: pixel-shuffle + softmax over 25 ----------------
// grid 64 = (n, hgroup of 4); 256 threads = hsub(4) x w(64)
__global__ void k_softmax() {
    int b = blockIdx.x; int n = b >> 4;
    int h = (b & 15) * 4 + (threadIdx.x >> 6);
    int w = threadIdx.x & 63;
    const float* base = g_mlog + (size_t)n * MC * PIX + h * WS + w;
    for (int q = 0; q < 4; q++) {
        float v[25];
        float mx = -1e30f;
        #pragma unroll
        for (int k = 0; k < 25; k++) {
            v[k] = base[(k * 4 + q) * PIX];
            mx = fmaxf(mx, v[k]);
        }
        float s = 0.f;
        #pragma unroll
        for (int k = 0; k < 25; k++) { v[k] = __expf(v[k] - mx); s += v[k]; }
        float inv = 1.f / s;
        int ry = q >> 1, rx = q & 1;
        int i = 2 * h + ry, j = 2 * w + rx;
        float* o = g_mask + ((size_t)(n * HO + i) * WO + j) * KK2;
        #pragma unroll
        for (int k = 0; k < 25; k++) o[k] = v[k] * inv;
    }
}

// ---------------- K4: CARAFE on y + bias -> x (pre-BN) [R1 version] ----------------
// grid 2048 = (n, h, ocChunk of 32); 256 threads: j (128) x oc half (16)
__global__ __launch_bounds__(256) void k_carafe(float* __restrict__ out) {
    int b = blockIdx.x;
    int n   = b >> 9;
    int h   = (b >> 3) & 63;
    int oc0 = (b & 7) * 32;
    int tid = threadIdx.x;
    int j   = tid & 127;
    int ocg = (tid >> 7) * 16;
    int w   = j >> 1;

    __shared__ float ys[32][5][68];
    for (int idx = tid; idx < 32 * 5 * 68; idx += 256) {
        int oc = idx / 340; int rem = idx % 340; int r = rem / 68; int x = rem % 68;
        int gh = h - 2 + r, gw = x - 2;
        float v = 0.f;
        if (gh >= 0 && gh < 64 && gw >= 0 && gw < 64)
            v = g_y[((n * CC + oc0 + oc) * HS + gh) * WS + gw];
        ys[oc][r][x] = v;
    }
    __syncthreads();

    float m0[25], m1[25];
    {
        const float* mp0 = g_mask + ((size_t)(n * HO + 2 * h)     * WO + j) * KK2;
        const float* mp1 = g_mask + ((size_t)(n * HO + 2 * h + 1) * WO + j) * KK2;
        #pragma unroll
        for (int k = 0; k < 25; k++) { m0[k] = mp0[k]; m1[k] = mp1[k]; }
    }

    for (int o = 0; o < 16; o++) {
        int oc = ocg + o;
        float a0 = 0.f, a1 = 0.f;
        #pragma unroll
        for (int dy = 0; dy < 5; dy++) {
            #pragma unroll
            for (int dx = 0; dx < 5; dx++) {
                float yv = ys[oc][dy][w + dx];
                a0 += m0[dy * 5 + dx] * yv;
                a1 += m1[dy * 5 + dx] * yv;
            }
        }
        float be = g_beff[oc0 + oc];
        size_t co = (size_t)(n * CC + oc0 + oc);
        out[(co * HO + 2 * h)     * WO + j] = a0 + be;
        out[(co * HO + 2 * h + 1) * WO + j] = a1 + be;
    }
}

// ---------------- K5a: BN reduction (sum, sumsq per channel) ----------------
__global__ void k_bnred(const float* __restrict__ x) {
    int b = blockIdx.x;
    int o = b & 255;
    const float* p = x + (size_t)b * OPIX;
    float s = 0.f, ss = 0.f;
    for (int idx = threadIdx.x; idx < OPIX; idx += 256) {
        float v = p[idx];
        s += v; ss += v * v;
    }
    #pragma unroll
    for (int off = 16; off > 0; off >>= 1) {
        s  += __shfl_down_sync(0xffffffffu, s, off);
        ss += __shfl_down_sync(0xffffffffu, ss, off);
    }
    __shared__ float rs[8], rss[8];
    if ((threadIdx.x & 31) == 0) { rs[threadIdx.x >> 5] = s; rss[threadIdx.x >> 5] = ss; }
    __syncthreads();
    if (threadIdx.x == 0) {
        float S = 0.f, SS = 0.f;
        #pragma unroll
        for (int i = 0; i < 8; i++) { S += rs[i]; SS += rss[i]; }
        atomicAdd(&g_sum[o], S);
        atomicAdd(&g_sumsq[o], SS);
    }
}

// ---------------- K5b: BN scale/shift ----------------
__global__ void k_bnparam(const float* __restrict__ gamma, const float* __restrict__ beta) {
    int o = threadIdx.x;
    float cnt = (float)(NN * HO * WO);
    float mean = g_sum[o] / cnt;
    float var  = g_sumsq[o] / cnt - mean * mean;
    float sc   = gamma[o] * rsqrtf(var + BN_EPS);
    g_scale[o] = sc;
    g_shift[o] = beta[o] - mean * sc;
}

// ---------------- K6: normalize + affine + ReLU in-place (float4) ----------------
__global__ void k_bnapply(float* __restrict__ x) {
    int idx = blockIdx.x * 256 + threadIdx.x;
    int o = (idx >> 12) & 255;
    float4 v = reinterpret_cast<float4*>(x)[idx];
    float sc = g_scale[o], sh = g_shift[o];
    v.x = fmaxf(v.x * sc + sh, 0.f);
    v.y = fmaxf(v.y * sc + sh, 0.f);
    v.z = fmaxf(v.z * sc + sh, 0.f);
    v.w = fmaxf(v.w * sc + sh, 0.f);
    reinterpret_cast<float4*>(x)[idx] = v;
}

// ---------------- launcher ----------------
extern "C" void kernel_launch(void* const* d_in, const int* in_sizes, int n_in,
                              void* d_out, int out_size) {
    const float* high  = (const float*)d_in[1];
    const float* wcc   = (const float*)d_in[2];
    const float* bcc   = (const float*)d_in[3];
    const float* wce   = (const float*)d_in[4];
    const float* bce   = (const float*)d_in[5];
    const float* wc2   = (const float*)d_in[6];
    const float* bc2   = (const float*)d_in[7];
    const float* wb    = (const float*)d_in[8];
    const float* gamma = (const float*)d_in[9];
    const float* beta  = (const float*)d_in[10];
    float* out = (float*)d_out;

    k_fold    <<<256, 256>>>(wb, wc2, bc2);
    k_gemm    <<<320, 256>>>(high, wcc, bcc);
    k_encode  <<<256, 128>>>(wce, bce);
    k_softmax <<<64, 256>>>();
    k_carafe  <<<2048, 256>>>(out);
    k_bnred   <<<1024, 256>>>(out);
    k_bnparam <<<1, 256>>>(gamma, beta);
    k_bnapply <<<16384, 256>>>(out);
}

// round 4
// speedup vs baseline: 1.5938x; 1.5938x over previous
#include <cuda_runtime.h>

// Problem constants
#define NN   4
#define CC   256
#define HS   64
#define WS   64
#define PIX  4096
#define COMPC 64
#define MC   100      // K*K*R*R
#define KK2  25
#define HO   128
#define WO   128
#define OPIX 16384
#define BN_EPS 1e-5f

// ---------------- device scratch (no allocation allowed) ----------------
__device__ float g_comp[NN * COMPC * PIX];         // compressed features
__device__ float g_mlog[NN * MC * PIX];            // encoder logits
__device__ float g_mask[NN * HO * WO * KK2];       // softmaxed masks, [n][i][j][k]
__device__ float g_y   [NN * CC * PIX];            // W_eff @ high
__device__ float g_weff [CC * CC];                 // [o][c]
__device__ float g_wefft[CC * CC];                 // transposed [c][o]
__device__ float g_wcct [CC * COMPC];              // compressor transposed [ic][oc]
__device__ float g_wcet [576 * 100];               // encoder transposed [(ic*9+r)][oc]
__device__ float g_beff[CC];
__device__ float g_sum [CC];
__device__ float g_sumsq[CC];
__device__ float g_scale[CC];
__device__ float g_shift[CC];

// ---------------- K0: fold weights + transposes + zero BN accumulators ----------------
__global__ void k_fold(const float* __restrict__ wb,
                       const float* __restrict__ wc2,
                       const float* __restrict__ bc2,
                       const float* __restrict__ wcc) {
    int o = blockIdx.x;
    int c = threadIdx.x;
    const float* wbo = wb + o * 512;
    float acc = wbo[256 + c];
    for (int m = 0; m < 256; m++)
        acc += wbo[m] * wc2[m * 256 + c];
    g_weff[o * 256 + c] = acc;
    g_wefft[c * 256 + o] = acc;
    if (o < 64) g_wcct[c * 64 + o] = wcc[o * 256 + c];

    __shared__ float red[256];
    red[c] = wbo[c] * bc2[c];
    __syncthreads();
    for (int s = 128; s > 0; s >>= 1) {
        if (c < s) red[c] += red[c + s];
        __syncthreads();
    }
    if (c == 0) g_beff[o] = red[0];
    if (o == 0) { g_sum[c] = 0.f; g_sumsq[c] = 0.f; }
}

// ---------------- K0b: transpose encoder weights [oc][ic*9] -> [(ic*9)][oc] ----------------
__global__ void k_trans(const float* __restrict__ wce) {
    int b = blockIdx.x;          // 0..575 = ic*9 + r
    int t = threadIdx.x;         // 0..99 = oc
    g_wcet[b * 100 + t] = wce[t * 576 + b];
}

// ---------------- K1: channel compressor 1x1 (256 -> 64) ----------------
// grid 256 = (n,h); 128 threads: w-pair (tid&31, +32) x 16 oc (tid>>5)
__global__ __launch_bounds__(128) void k_compress(const float* __restrict__ hi,
                                                  const float* __restrict__ bcc) {
    int b = blockIdx.x; int n = b >> 6; int h = b & 63;
    int tid = threadIdx.x;
    int w2 = tid & 31; int og = tid >> 5;
    __shared__ float xs[64][64];
    __shared__ __align__(16) float ws[64][68];   // [cl][oc] padded
    float acc0[16], acc1[16];
    #pragma unroll
    for (int o = 0; o < 16; o++) { float bv = bcc[og * 16 + o]; acc0[o] = bv; acc1[o] = bv; }

    for (int cc0 = 0; cc0 < 256; cc0 += 64) {
        for (int idx = tid; idx < 4096; idx += 128) {
            int cl = idx >> 6, w = idx & 63;
            xs[cl][w] = hi[((n * CC + cc0 + cl) * HS + h) * WS + w];
        }
        for (int idx = tid; idx < 4096; idx += 128) {
            int cl = idx >> 6, oc = idx & 63;
            ws[cl][oc] = g_wcct[(cc0 + cl) * 64 + oc];
        }
        __syncthreads();
        for (int cl = 0; cl < 64; cl++) {
            float x0 = xs[cl][w2], x1 = xs[cl][w2 + 32];
            const float4* wr = (const float4*)&ws[cl][og * 16];
            #pragma unroll
            for (int q = 0; q < 4; q++) {
                float4 wv = wr[q];
                acc0[q*4+0] += wv.x * x0;  acc1[q*4+0] += wv.x * x1;
                acc0[q*4+1] += wv.y * x0;  acc1[q*4+1] += wv.y * x1;
                acc0[q*4+2] += wv.z * x0;  acc1[q*4+2] += wv.z * x1;
                acc0[q*4+3] += wv.w * x0;  acc1[q*4+3] += wv.w * x1;
            }
        }
        __syncthreads();
    }
    #pragma unroll
    for (int o = 0; o < 16; o++) {
        int oc = og * 16 + o;
        g_comp[((n * COMPC + oc) * HS + h) * WS + w2]      = acc0[o];
        g_comp[((n * COMPC + oc) * HS + h) * WS + w2 + 32] = acc1[o];
    }
}

// ---------------- K2: content encoder 3x3 (64 -> 100) ----------------
// grid 256 = (n,h); 128 threads: w-pair x 25 oc group (tid>>5)
__global__ __launch_bounds__(128) void k_encode(const float* __restrict__ bce) {
    int b = blockIdx.x; int n = b >> 6; int h = b & 63;
    int tid = threadIdx.x;
    int w2 = tid & 31; int og = tid >> 5;
    __shared__ float xs[8][3][66];
    __shared__ __align__(16) float ws[72][112];   // [(cl*9+r)][og*28 + oc%25]
    float acc0[25], acc1[25];
    #pragma unroll
    for (int o = 0; o < 25; o++) { acc0[o] = 0.f; acc1[o] = 0.f; }

    // zero the pad columns once (cols og*28+{25,26,27})
    for (int i = tid; i < 72 * 12; i += 128) {
        int r = i / 12; int q = i % 12;
        ws[r][(q >> 2) * 28 + 25 + (q & 3) % 3] = 0.f;  // touches 25,26,27 (25 twice, harmless)
    }

    for (int cc0 = 0; cc0 < 64; cc0 += 8) {
        __syncthreads();
        for (int idx = tid; idx < 8 * 3 * 66; idx += 128) {
            int cl = idx / 198; int rem = idx % 198; int r = rem / 66; int x = rem % 66;
            int gh = h - 1 + r, gw = x - 1;
            float v = 0.f;
            if (gh >= 0 && gh < 64 && gw >= 0 && gw < 64)
                v = g_comp[((n * COMPC + cc0 + cl) * HS + gh) * WS + gw];
            xs[cl][r][x] = v;
        }
        for (int idx = tid; idx < 7200; idx += 128) {
            int r72 = idx / 100; int oc = idx % 100;
            ws[r72][(oc / 25) * 28 + (oc % 25)] = g_wcet[(cc0 * 9 + r72) * 100 + oc];
        }
        __syncthreads();
        for (int cl = 0; cl < 8; cl++) {
            #pragma unroll
            for (int ky = 0; ky < 3; ky++) {
                #pragma unroll
                for (int kx = 0; kx < 3; kx++) {
                    float x0 = xs[cl][ky][w2 + kx];
                    float x1 = xs[cl][ky][w2 + 32 + kx];
                    const float4* wr = (const float4*)&ws[cl * 9 + ky * 3 + kx][og * 28];
                    #pragma unroll
                    for (int q = 0; q < 7; q++) {
                        float4 wv = wr[q];
                        int o = q * 4;
                        acc0[o] += wv.x * x0;  acc1[o] += wv.x * x1;
                        if (o + 1 < 25) { acc0[o+1] += wv.y * x0;  acc1[o+1] += wv.y * x1; }
                        if (o + 2 < 25) { acc0[o+2] += wv.z * x0;  acc1[o+2] += wv.z * x1; }
                        if (o + 3 < 25) { acc0[o+3] += wv.w * x0;  acc1[o+3] += wv.w * x1; }
                    }
                }
            }
        }
    }
    #pragma unroll
    for (int o = 0; o < 25; o++) {
        int oc = og * 25 + o;
        float bv = bce[oc];
        g_mlog[((n * MC + oc) * HS + h) * WS + w2]      = acc0[o] + bv;
        g_mlog[((n * MC + oc) * HS + h) * WS + w2 + 32] = acc1[o] + bv;
    }
}

// ---------------- K2.5: y = W_eff @ high ----------------
// grid 256 = (n,h); 256 threads: w-pair x 32 oc (8 groups)
__global__ __launch_bounds__(256) void k_ymix(const float* __restrict__ hi) {
    int b = blockIdx.x; int n = b >> 6; int h = b & 63;
    int tid = threadIdx.x;
    int w2 = tid & 31; int og = tid >> 5;  // 8 groups of 32 oc
    __shared__ float xs[32][64];
    __shared__ __align__(16) float ws[32][260];   // [cl][oc] padded
    float acc0[32], acc1[32];
    #pragma unroll
    for (int o = 0; o < 32; o++) { acc0[o] = 0.f; acc1[o] = 0.f; }

    for (int cc0 = 0; cc0 < 256; cc0 += 32) {
        for (int idx = tid; idx < 2048; idx += 256) {
            int cl = idx >> 6, w = idx & 63;
            xs[cl][w] = hi[((n * CC + cc0 + cl) * HS + h) * WS + w];
        }
        for (int idx = tid; idx < 8192; idx += 256) {
            int cl = idx >> 8, oc = idx & 255;
            ws[cl][oc] = g_wefft[(cc0 + cl) * 256 + oc];
        }
        __syncthreads();
        for (int cl = 0; cl < 32; cl++) {
            float x0 = xs[cl][w2], x1 = xs[cl][w2 + 32];
            const float4* wr = (const float4*)&ws[cl][og * 32];
            #pragma unroll
            for (int q = 0; q < 8; q++) {
                float4 wv = wr[q];
                acc0[q*4+0] += wv.x * x0;  acc1[q*4+0] += wv.x * x1;
                acc0[q*4+1] += wv.y * x0;  acc1[q*4+1] += wv.y * x1;
                acc0[q*4+2] += wv.z * x0;  acc1[q*4+2] += wv.z * x1;
                acc0[q*4+3] += wv.w * x0;  acc1[q*4+3] += wv.w * x1;
            }
        }
        __syncthreads();
    }
    #pragma unroll
    for (int o = 0; o < 32; o++) {
        int oc = og * 32 + o;
        g_y[((n * CC + oc) * HS + h) * WS + w2]      = acc0[o];
        g_y[((n * CC + oc) * HS + h) * WS + w2 + 32] = acc1[o];
    }
}

// ---------------- K3: pixel-shuffle + softmax over 25 ----------------
// grid 256 = (n,h); 256 threads = q(4) x w(64)
__global__ void k_softmax() {
    int b = blockIdx.x; int n = b >> 6; int h = b & 63;
    int q = threadIdx.x >> 6;
    int w = threadIdx.x & 63;
    const float* base = g_mlog + (size_t)n * MC * PIX + h * WS + w;
    float v[25];
    float mx = -1e30f;
    #pragma unroll
    for (int k = 0; k < 25; k++) {
        v[k] = base[(k * 4 + q) * PIX];
        mx = fmaxf(mx, v[k]);
    }
    float s = 0.f;
    #pragma unroll
    for (int k = 0; k < 25; k++) { v[k] = __expf(v[k] - mx); s += v[k]; }
    float inv = 1.f / s;
    int i = 2 * h + (q >> 1), j = 2 * w + (q & 1);
    float* o = g_mask + ((size_t)(n * HO + i) * WO + j) * KK2;
    #pragma unroll
    for (int k = 0; k < 25; k++) o[k] = v[k] * inv;
}

// ---------------- K4: CARAFE on y + bias -> out (pre-BN) [R1 version] ----------------
__global__ __launch_bounds__(256) void k_carafe(float* __restrict__ out) {
    int b = blockIdx.x;
    int n   = b >> 9;
    int h   = (b >> 3) & 63;
    int oc0 = (b & 7) * 32;
    int tid = threadIdx.x;
    int j   = tid & 127;
    int ocg = (tid >> 7) * 16;
    int w   = j >> 1;

    __shared__ float ys[32][5][68];
    for (int idx = tid; idx < 32 * 5 * 68; idx += 256) {
        int oc = idx / 340; int rem = idx % 340; int r = rem / 68; int x = rem % 68;
        int gh = h - 2 + r, gw = x - 2;
        float v = 0.f;
        if (gh >= 0 && gh < 64 && gw >= 0 && gw < 64)
            v = g_y[((n * CC + oc0 + oc) * HS + gh) * WS + gw];
        ys[oc][r][x] = v;
    }
    __syncthreads();

    float m0[25], m1[25];
    {
        const float* mp0 = g_mask + ((size_t)(n * HO + 2 * h)     * WO + j) * KK2;
        const float* mp1 = g_mask + ((size_t)(n * HO + 2 * h + 1) * WO + j) * KK2;
        #pragma unroll
        for (int k = 0; k < 25; k++) { m0[k] = mp0[k]; m1[k] = mp1[k]; }
    }

    for (int o = 0; o < 16; o++) {
        int oc = ocg + o;
        float a0 = 0.f, a1 = 0.f;
        #pragma unroll
        for (int dy = 0; dy < 5; dy++) {
            #pragma unroll
            for (int dx = 0; dx < 5; dx++) {
                float yv = ys[oc][dy][w + dx];
                a0 += m0[dy * 5 + dx] * yv;
                a1 += m1[dy * 5 + dx] * yv;
            }
        }
        float be = g_beff[oc0 + oc];
        size_t co = (size_t)(n * CC + oc0 + oc);
        out[(co * HO + 2 * h)     * WO + j] = a0 + be;
        out[(co * HO + 2 * h + 1) * WO + j] = a1 + be;
    }
}

// ---------------- K5a: BN reduction ----------------
__global__ void k_bnred(const float* __restrict__ x) {
    int b = blockIdx.x;
    int o = b & 255;
    const float* p = x + (size_t)b * OPIX;
    float s = 0.f, ss = 0.f;
    for (int idx = threadIdx.x; idx < OPIX; idx += 256) {
        float v = p[idx];
        s += v; ss += v * v;
    }
    #pragma unroll
    for (int off = 16; off > 0; off >>= 1) {
        s  += __shfl_down_sync(0xffffffffu, s, off);
        ss += __shfl_down_sync(0xffffffffu, ss, off);
    }
    __shared__ float rs[8], rss[8];
    if ((threadIdx.x & 31) == 0) { rs[threadIdx.x >> 5] = s; rss[threadIdx.x >> 5] = ss; }
    __syncthreads();
    if (threadIdx.x == 0) {
        float S = 0.f, SS = 0.f;
        #pragma unroll
        for (int i = 0; i < 8; i++) { S += rs[i]; SS += rss[i]; }
        atomicAdd(&g_sum[o], S);
        atomicAdd(&g_sumsq[o], SS);
    }
}

// ---------------- K5b: BN scale/shift ----------------
__global__ void k_bnparam(const float* __restrict__ gamma, const float* __restrict__ beta) {
    int o = threadIdx.x;
    float cnt = (float)(NN * HO * WO);
    float mean = g_sum[o] / cnt;
    float var  = g_sumsq[o] / cnt - mean * mean;
    float sc   = gamma[o] * rsqrtf(var + BN_EPS);
    g_scale[o] = sc;
    g_shift[o] = beta[o] - mean * sc;
}

// ---------------- K6: normalize + affine + ReLU in-place (float4) ----------------
__global__ void k_bnapply(float* __restrict__ x) {
    int idx = blockIdx.x * 256 + threadIdx.x;
    int o = (idx >> 12) & 255;
    float4 v = reinterpret_cast<float4*>(x)[idx];
    float sc = g_scale[o], sh = g_shift[o];
    v.x = fmaxf(v.x * sc + sh, 0.f);
    v.y = fmaxf(v.y * sc + sh, 0.f);
    v.z = fmaxf(v.z * sc + sh, 0.f);
    v.w = fmaxf(v.w * sc + sh, 0.f);
    reinterpret_cast<float4*>(x)[idx] = v;
}

// ---------------- launcher ----------------
extern "C" void kernel_launch(void* const* d_in, const int* in_sizes, int n_in,
                              void* d_out, int out_size) {
    const float* high  = (const float*)d_in[1];
    const float* wcc   = (const float*)d_in[2];
    const float* bcc   = (const float*)d_in[3];
    const float* wce   = (const float*)d_in[4];
    const float* bce   = (const float*)d_in[5];
    const float* wc2   = (const float*)d_in[6];
    const float* bc2   = (const float*)d_in[7];
    const float* wb    = (const float*)d_in[8];
    const float* gamma = (const float*)d_in[9];
    const float* beta  = (const float*)d_in[10];
    float* out = (float*)d_out;

    k_fold    <<<256, 256>>>(wb, wc2, bc2, wcc);
    k_trans   <<<576, 100>>>(wce);
    k_compress<<<256, 128>>>(high, bcc);
    k_encode  <<<256, 128>>>(bce);
    k_ymix    <<<256, 256>>>(high);
    k_softmax <<<256, 256>>>();
    k_carafe  <<<2048, 256>>>(out);
    k_bnred   <<<1024, 256>>>(out);
    k_bnparam <<<1, 256>>>(gamma, beta);
    k_bnapply <<<16384, 256>>>(out);
}